// round 1
// baseline (speedup 1.0000x reference)
#include <cuda_runtime.h>
#include <cstdint>

// GeometricLoss: N=8192 points (2D), k=5 nearest neighbors (excl. self),
// mean over (i, nbr) of ||outputs[i]-outputs[nbr]||_2 over C=16 channels.
//
// Inputs (metadata order): d_in[0]=outputs f32[8192*16], d_in[1]=points f32[8192*2],
// d_in[2]=k (int, ==5, hardcoded). Output: single f32 scalar.

#define NPTS 8192
#define NCH 16
#define KNN 5
#define TPB 256

// Scratch for per-query partial sums (no cudaMalloc allowed).
__device__ float g_partial[NPTS];

__global__ __launch_bounds__(TPB, 8)
void knn_loss_kernel(const float* __restrict__ outputs,
                     const float2* __restrict__ points) {
    const int qi  = blockIdx.x;
    const int tid = threadIdx.x;
    const int lane = tid & 31;
    const int warp = tid >> 5;

    const float2 q = points[qi];

    // ---- per-thread top-6 over strided candidates (sorted ascending) ----
    unsigned long long best[6];
#pragma unroll
    for (int t = 0; t < 6; t++) best[t] = 0xFFFFFFFFFFFFFFFFULL;

    for (int j = tid; j < NPTS; j += TPB) {
        float2 p = points[j];
        float dx = q.x - p.x;
        float dy = q.y - p.y;
        float d2 = dx * dx + dy * dy;
        // nonneg f32: bit pattern preserves ordering; low 32 bits = index
        // => ties broken by smaller index, matching jax.lax.top_k.
        unsigned long long key =
            ((unsigned long long)__float_as_uint(d2) << 32) | (unsigned)j;
        if (key < best[5]) {
            best[5] = key;
#pragma unroll
            for (int t = 5; t > 0; t--) {
                if (best[t] < best[t - 1]) {
                    unsigned long long tmp = best[t];
                    best[t] = best[t - 1];
                    best[t - 1] = tmp;
                }
            }
        }
    }

    // ---- stage candidates to smem, run 6 arg-min passes ----
    __shared__ unsigned long long cand[TPB * 6];
    __shared__ unsigned long long warp_min[TPB / 32];
    __shared__ unsigned long long sel[6];

#pragma unroll
    for (int t = 0; t < 6; t++) cand[tid * 6 + t] = best[t];
    __syncthreads();

    for (int pass = 0; pass < 6; pass++) {
        // local min over this thread's 6 owned slots (they stay sorted? no —
        // invalidation breaks order, so scan all 6)
        unsigned long long lmin = 0xFFFFFFFFFFFFFFFFULL;
#pragma unroll
        for (int t = 0; t < 6; t++) {
            unsigned long long v = cand[tid * 6 + t];
            if (v < lmin) lmin = v;
        }
        // warp reduce min
#pragma unroll
        for (int off = 16; off > 0; off >>= 1) {
            unsigned long long o = __shfl_down_sync(0xFFFFFFFFu, lmin, off);
            if (o < lmin) lmin = o;
        }
        if (lane == 0) warp_min[warp] = lmin;
        __syncthreads();
        if (tid == 0) {
            unsigned long long m = warp_min[0];
#pragma unroll
            for (int w = 1; w < TPB / 32; w++)
                if (warp_min[w] < m) m = warp_min[w];
            sel[pass] = m;
        }
        __syncthreads();
        // invalidate the selected (unique) key wherever it lives
        unsigned long long chosen = sel[pass];
#pragma unroll
        for (int t = 0; t < 6; t++) {
            if (cand[tid * 6 + t] == chosen)
                cand[tid * 6 + t] = 0xFFFFFFFFFFFFFFFFULL;
        }
        __syncthreads();
    }

    // ---- epilogue: 5 neighbor norms (sel[0] is self), warp 0 only ----
    if (warp == 0) {
        float s = 0.0f;
        if (lane < KNN) {
            int nb = (int)(sel[lane + 1] & 0xFFFFFFFFULL);
            const float* oq = outputs + (size_t)qi * NCH;
            const float* on = outputs + (size_t)nb * NCH;
            float acc = 0.0f;
#pragma unroll
            for (int c = 0; c < NCH; c++) {
                float d = oq[c] - on[c];
                acc += d * d;
            }
            s = sqrtf(acc);
        }
#pragma unroll
        for (int off = 16; off > 0; off >>= 1)
            s += __shfl_down_sync(0xFFFFFFFFu, s, off);
        if (lane == 0) g_partial[qi] = s;
    }
}

__global__ void final_reduce_kernel(float* __restrict__ out) {
    __shared__ float sm[TPB];
    float acc = 0.0f;
    for (int j = threadIdx.x; j < NPTS; j += TPB) acc += g_partial[j];
    sm[threadIdx.x] = acc;
    __syncthreads();
    for (int st = TPB / 2; st > 0; st >>= 1) {
        if (threadIdx.x < st) sm[threadIdx.x] += sm[threadIdx.x + st];
        __syncthreads();
    }
    if (threadIdx.x == 0)
        out[0] = sm[0] / (float)(NPTS * KNN);
}

extern "C" void kernel_launch(void* const* d_in, const int* in_sizes, int n_in,
                              void* d_out, int out_size) {
    const float*  outputs = (const float*)d_in[0];
    const float2* points  = (const float2*)d_in[1];
    float* out = (float*)d_out;

    knn_loss_kernel<<<NPTS, TPB>>>(outputs, points);
    final_reduce_kernel<<<1, TPB>>>(out);
}

// round 2
// speedup vs baseline: 1.2890x; 1.2890x over previous
#include <cuda_runtime.h>
#include <cstdint>

// GeometricLoss: N=8192 2D points, k=5 NN (excl. self), mean of 16-ch L2 norms
// of output differences. One warp handles 2 queries; all points cached in smem.

#define NPTS 8192
#define NCH 16
#define KNN 5
#define TPB 256
#define QPW 2                       // queries per warp
#define WPB (TPB / 32)              // warps per block
#define QPB (WPB * QPW)             // queries per block = 16
#define NBLK (NPTS / QPB)           // 512 blocks
#define SENT 0x7F800000FFFFFFFFULL  // (inf_bits << 32) | 0xFFFFFFFF

__device__ float g_partial[NPTS];

extern __shared__ float2 pts_s[];

__device__ __forceinline__ void insert6(unsigned long long* b, float d2,
                                        int j, float& th) {
    unsigned long long key =
        ((unsigned long long)__float_as_uint(d2) << 32) | (unsigned)j;
    b[5] = key;  // guaranteed key < old b[5] because d2 < th (nonneg floats)
#pragma unroll
    for (int t = 5; t > 0; t--) {
        if (b[t] < b[t - 1]) {
            unsigned long long tmp = b[t];
            b[t] = b[t - 1];
            b[t - 1] = tmp;
        }
    }
    th = __uint_as_float((unsigned)(b[5] >> 32));
}

// Warp-collective: merge 32 sorted top-6 lists, compute the 5-neighbor norm
// sum for query qi, write per-query partial. b[] is destroyed.
__device__ __forceinline__ void finish_query(unsigned long long* b, int qi,
                                             const float* __restrict__ outputs,
                                             int lane) {
    unsigned long long mykey = SENT;  // lane r ends up holding rank-r key
    unsigned long long head = b[0];
#pragma unroll
    for (int r = 0; r < 6; r++) {
        unsigned long long v = head;
#pragma unroll
        for (int off = 16; off > 0; off >>= 1) {
            unsigned long long o = __shfl_xor_sync(0xFFFFFFFFu, v, off);
            if (o < v) v = o;
        }
        if (lane == r) mykey = v;
        if (head == v) {  // unique key -> exactly one owner advances
            head = b[1]; b[1] = b[2]; b[2] = b[3];
            b[3] = b[4]; b[4] = b[5]; b[5] = SENT;
        }
    }
    // ranks 1..5 are the k neighbors (rank 0 = self / global min key)
    float s = 0.0f;
    if (lane >= 1 && lane <= KNN) {
        int nb = (int)(mykey & 0xFFFFFFFFULL);
        const float4* oq = (const float4*)(outputs + (size_t)qi * NCH);
        const float4* on = (const float4*)(outputs + (size_t)nb * NCH);
        float acc = 0.0f;
#pragma unroll
        for (int c = 0; c < NCH / 4; c++) {
            float4 a = oq[c];
            float4 bb = on[c];
            float d;
            d = a.x - bb.x; acc = fmaf(d, d, acc);
            d = a.y - bb.y; acc = fmaf(d, d, acc);
            d = a.z - bb.z; acc = fmaf(d, d, acc);
            d = a.w - bb.w; acc = fmaf(d, d, acc);
        }
        s = sqrtf(acc);
    }
#pragma unroll
    for (int off = 16; off > 0; off >>= 1)
        s += __shfl_xor_sync(0xFFFFFFFFu, s, off);
    if (lane == 0) g_partial[qi] = s;
}

__global__ __launch_bounds__(TPB, 3)
void knn_loss_kernel(const float* __restrict__ outputs,
                     const float* __restrict__ points) {
    const int tid = threadIdx.x;
    const int lane = tid & 31;
    const int warp = tid >> 5;

    // cooperative smem fill: 8192 float2 = 4096 float4
    {
        float4* dst = (float4*)pts_s;
        const float4* src = (const float4*)points;
#pragma unroll
        for (int i = 0; i < NPTS / 2 / TPB; i++)
            dst[tid + i * TPB] = src[tid + i * TPB];
    }
    __syncthreads();

    const int qi0 = (blockIdx.x * WPB + warp) * QPW;
    const int qi1 = qi0 + 1;
    const float2 q0 = pts_s[qi0];
    const float2 q1 = pts_s[qi1];

    unsigned long long b0[6], b1[6];
#pragma unroll
    for (int t = 0; t < 6; t++) { b0[t] = SENT; b1[t] = SENT; }
    float th0 = __int_as_float(0x7F800000);
    float th1 = th0;

#pragma unroll 4
    for (int j = lane; j < NPTS; j += 32) {
        float2 p = pts_s[j];
        float dx0 = q0.x - p.x;
        float dy0 = q0.y - p.y;
        float d20 = fmaf(dy0, dy0, dx0 * dx0);
        float dx1 = q1.x - p.x;
        float dy1 = q1.y - p.y;
        float d21 = fmaf(dy1, dy1, dx1 * dx1);
        if (d20 < th0) insert6(b0, d20, j, th0);
        if (d21 < th1) insert6(b1, d21, j, th1);
    }

    finish_query(b0, qi0, outputs, lane);
    finish_query(b1, qi1, outputs, lane);
}

__global__ void final_reduce_kernel(float* __restrict__ out) {
    __shared__ float sm[TPB];
    float acc = 0.0f;
    for (int j = threadIdx.x; j < NPTS; j += TPB) acc += g_partial[j];
    sm[threadIdx.x] = acc;
    __syncthreads();
    for (int st = TPB / 2; st > 0; st >>= 1) {
        if (threadIdx.x < st) sm[threadIdx.x] += sm[threadIdx.x + st];
        __syncthreads();
    }
    if (threadIdx.x == 0)
        out[0] = sm[0] / (float)(NPTS * KNN);
}

extern "C" void kernel_launch(void* const* d_in, const int* in_sizes, int n_in,
                              void* d_out, int out_size) {
    const float* outputs = (const float*)d_in[0];
    const float* points  = (const float*)d_in[1];
    float* out = (float*)d_out;

    cudaFuncSetAttribute(knn_loss_kernel,
                         cudaFuncAttributeMaxDynamicSharedMemorySize,
                         NPTS * sizeof(float2));
    knn_loss_kernel<<<NBLK, TPB, NPTS * sizeof(float2)>>>(outputs, points);
    final_reduce_kernel<<<1, TPB>>>(out);
}

// round 3
// speedup vs baseline: 1.4593x; 1.1321x over previous
#include <cuda_runtime.h>
#include <cstdint>

// GeometricLoss: N=8192 2D points, k=5 NN (excl. self), mean of 16-ch L2 norms
// of output differences. Warp-collective top-6 with ballot-gated slow path,
// 4 queries/warp, all points cached in smem, fused final reduction.

#define NPTS 8192
#define NCH 16
#define KNN 5
#define TPB 256
#define QPW 4                       // queries per warp
#define WPB (TPB / 32)              // 8 warps per block
#define QPB (WPB * QPW)             // 32 queries per block
#define NBLK (NPTS / QPB)           // 256 blocks
#define FULLM 0xFFFFFFFFu
#define SENT 0x7F800000FFFFFFFFULL  // (inf_bits << 32) | 0xFFFFFFFF

__device__ float g_partial[NPTS];
__device__ unsigned g_ticket = 0;

extern __shared__ float2 pts_s[];

// Uniform (all lanes execute identically) sorted insert into replicated top-6.
// Precondition: d2 < th (so key < b[5]).
__device__ __forceinline__ void insert6(unsigned long long* b, float d2,
                                        int j, float& th) {
    unsigned long long key =
        ((unsigned long long)__float_as_uint(d2) << 32) | (unsigned)j;
    b[5] = key;
#pragma unroll
    for (int t = 5; t > 0; t--) {
        if (b[t] < b[t - 1]) {
            unsigned long long tmp = b[t];
            b[t] = b[t - 1];
            b[t - 1] = tmp;
        }
    }
    th = __uint_as_float((unsigned)(b[5] >> 32));
}

// Slow path: process ballot hits in increasing lane (=index) order, uniformly.
__device__ __forceinline__ void scan_hits(unsigned msk, float d2, int jbase,
                                          unsigned long long* b, float& th) {
    while (msk) {
        int src = __ffs(msk) - 1;
        msk &= msk - 1;
        float d = __shfl_sync(FULLM, d2, src);
        if (d < th)  // th may have tightened; uniform predicate
            insert6(b, d, jbase + src, th);
    }
}

// b[] is replicated/uniform across the warp: ranks 0..5 are just b[0..5].
// Rank 0 is self (d2 == 0). Lanes 1..5 compute neighbor norms.
__device__ __forceinline__ void finish_query(const unsigned long long* b,
                                             int qi,
                                             const float* __restrict__ outputs,
                                             int lane) {
    float s = 0.0f;
    if (lane >= 1 && lane <= KNN) {
        int nb = (int)(b[lane] & 0xFFFFFFFFULL);
        const float4* oq = (const float4*)(outputs + (size_t)qi * NCH);
        const float4* on = (const float4*)(outputs + (size_t)nb * NCH);
        float acc = 0.0f;
#pragma unroll
        for (int c = 0; c < NCH / 4; c++) {
            float4 a = oq[c];
            float4 bb = on[c];
            float d;
            d = a.x - bb.x; acc = fmaf(d, d, acc);
            d = a.y - bb.y; acc = fmaf(d, d, acc);
            d = a.z - bb.z; acc = fmaf(d, d, acc);
            d = a.w - bb.w; acc = fmaf(d, d, acc);
        }
        s = sqrtf(acc);
    }
#pragma unroll
    for (int off = 16; off > 0; off >>= 1)
        s += __shfl_xor_sync(FULLM, s, off);
    if (lane == 0) g_partial[qi] = s;
}

__global__ __launch_bounds__(TPB)
void knn_loss_kernel(const float* __restrict__ outputs,
                     const float* __restrict__ points,
                     float* __restrict__ out) {
    const int tid = threadIdx.x;
    const int lane = tid & 31;
    const int warp = tid >> 5;

    // cooperative smem fill: 8192 float2 = 4096 float4
    {
        float4* dst = (float4*)pts_s;
        const float4* src = (const float4*)points;
#pragma unroll
        for (int i = 0; i < NPTS / 2 / TPB; i++)
            dst[tid + i * TPB] = src[tid + i * TPB];
    }
    __syncthreads();

    const int qb = (blockIdx.x * WPB + warp) * QPW;
    const float2 q0 = pts_s[qb + 0];
    const float2 q1 = pts_s[qb + 1];
    const float2 q2 = pts_s[qb + 2];
    const float2 q3 = pts_s[qb + 3];

    unsigned long long b0[6], b1[6], b2[6], b3[6];
#pragma unroll
    for (int t = 0; t < 6; t++) { b0[t] = SENT; b1[t] = SENT;
                                  b2[t] = SENT; b3[t] = SENT; }
    const float finf = __int_as_float(0x7F800000);
    float th0 = finf, th1 = finf, th2 = finf, th3 = finf;

#pragma unroll 2
    for (int t = 0; t < NPTS / 32; t++) {
        const int jbase = t * 32;
        float2 p = pts_s[jbase + lane];

        float dx, dy;
        dx = q0.x - p.x; dy = q0.y - p.y;
        float d20 = fmaf(dy, dy, dx * dx);
        dx = q1.x - p.x; dy = q1.y - p.y;
        float d21 = fmaf(dy, dy, dx * dx);
        dx = q2.x - p.x; dy = q2.y - p.y;
        float d22 = fmaf(dy, dy, dx * dx);
        dx = q3.x - p.x; dy = q3.y - p.y;
        float d23 = fmaf(dy, dy, dx * dx);

        unsigned m0 = __ballot_sync(FULLM, d20 < th0);
        unsigned m1 = __ballot_sync(FULLM, d21 < th1);
        unsigned m2 = __ballot_sync(FULLM, d22 < th2);
        unsigned m3 = __ballot_sync(FULLM, d23 < th3);
        if (m0) scan_hits(m0, d20, jbase, b0, th0);
        if (m1) scan_hits(m1, d21, jbase, b1, th1);
        if (m2) scan_hits(m2, d22, jbase, b2, th2);
        if (m3) scan_hits(m3, d23, jbase, b3, th3);
    }

    finish_query(b0, qb + 0, outputs, lane);
    finish_query(b1, qb + 1, outputs, lane);
    finish_query(b2, qb + 2, outputs, lane);
    finish_query(b3, qb + 3, outputs, lane);

    // ---- fused final reduction: last block to finish sums g_partial ----
    __syncthreads();
    __shared__ bool is_last;
    if (tid == 0) {
        __threadfence();
        unsigned tk = atomicAdd(&g_ticket, 1);
        is_last = (tk == NBLK - 1);
    }
    __syncthreads();
    if (is_last) {
        __threadfence();
        float acc = 0.0f;
        for (int j = tid; j < NPTS; j += TPB) acc += g_partial[j];
        __shared__ float sm[TPB];
        sm[tid] = acc;
        __syncthreads();
        for (int st = TPB / 2; st > 0; st >>= 1) {
            if (tid < st) sm[tid] += sm[tid + st];
            __syncthreads();
        }
        if (tid == 0) {
            out[0] = sm[0] / (float)(NPTS * KNN);
            g_ticket = 0;  // reset for next graph replay
        }
    }
}

extern "C" void kernel_launch(void* const* d_in, const int* in_sizes, int n_in,
                              void* d_out, int out_size) {
    const float* outputs = (const float*)d_in[0];
    const float* points  = (const float*)d_in[1];
    float* out = (float*)d_out;

    cudaFuncSetAttribute(knn_loss_kernel,
                         cudaFuncAttributeMaxDynamicSharedMemorySize,
                         NPTS * sizeof(float2));
    knn_loss_kernel<<<NBLK, TPB, NPTS * sizeof(float2)>>>(outputs, points, out);
}

// round 4
// speedup vs baseline: 1.9711x; 1.3506x over previous
#include <cuda_runtime.h>
#include <cstdint>

// GeometricLoss: N=8192 2D points, k=5 NN (excl. self), mean of 16-ch L2 norms
// of output differences.
// R4: distributed warp top-6 (lane r holds rank r), ballot-gated slow path,
// 4 queries/warp, TPB=512 -> 128 fully-resident CTAs, fused reduction.

#define NPTS 8192
#define NCH 16
#define KNN 5
#define TPB 512
#define QPW 4                       // queries per warp
#define WPB (TPB / 32)              // 16 warps per block
#define QPB (WPB * QPW)             // 64 queries per block
#define NBLK (NPTS / QPB)           // 128 blocks
#define FULLM 0xFFFFFFFFu
#define SENT 0x7F800000FFFFFFFFULL  // (inf_bits << 32) | 0xFFFFFFFF

__device__ float g_partial[NPTS];
__device__ unsigned g_ticket = 0;

extern __shared__ float2 pts_s[];

// Distributed top-6: lane r (r<6) holds the rank-r key; th (replicated) is the
// 6th-best d2. Keys (d2_bits<<32)|idx are unique & totally ordered, so the
// final top-6 set is insertion-order independent and exact.
struct TopK {
    unsigned long long key;
    float th;
};

__device__ __forceinline__ void tk_init(TopK& t) {
    t.key = SENT;
    t.th = __int_as_float(0x7F800000);
}

// Uniform insert of newkey (precondition: d2 < th). Sorted shift via shfl_up.
__device__ __forceinline__ void tk_insert(TopK& t, float d2, int j, int lane) {
    unsigned long long nk =
        ((unsigned long long)__float_as_uint(d2) << 32) | (unsigned)j;
    unsigned long long prev = __shfl_up_sync(FULLM, t.key, 1);
    // new[r] = nk < old[r-1] ? old[r-1] : (nk < old[r] ? nk : old[r])
    bool shift = (lane > 0) && (nk < prev);
    bool take  = nk < t.key;
    t.key = shift ? prev : (take ? nk : t.key);
    t.th = __uint_as_float(
        (unsigned)(__shfl_sync(FULLM, t.key, 5) >> 32));
}

// Slow path: walk ballot bits (uniform loop), re-check vs tightened th.
__device__ __forceinline__ void tk_hits(TopK& t, unsigned msk, float d2,
                                        int jbase, int lane) {
    do {
        int src = __ffs(msk) - 1;
        msk &= msk - 1;
        float d = __shfl_sync(FULLM, d2, src);
        if (d < t.th) tk_insert(t, d, jbase + src, lane);
    } while (msk);
}

// Rank 0 is self (d2==0, min key). Lanes 1..5 own the 5 neighbor keys.
__device__ __forceinline__ void finish_query(const TopK& t, int qi,
                                             const float* __restrict__ outputs,
                                             int lane) {
    float s = 0.0f;
    if (lane >= 1 && lane <= KNN) {
        int nb = (int)(t.key & 0xFFFFFFFFULL);
        const float4* oq = (const float4*)(outputs + (size_t)qi * NCH);
        const float4* on = (const float4*)(outputs + (size_t)nb * NCH);
        float acc = 0.0f;
#pragma unroll
        for (int c = 0; c < NCH / 4; c++) {
            float4 a = oq[c];
            float4 bb = on[c];
            float d;
            d = a.x - bb.x; acc = fmaf(d, d, acc);
            d = a.y - bb.y; acc = fmaf(d, d, acc);
            d = a.z - bb.z; acc = fmaf(d, d, acc);
            d = a.w - bb.w; acc = fmaf(d, d, acc);
        }
        s = sqrtf(acc);
    }
#pragma unroll
    for (int off = 16; off > 0; off >>= 1)
        s += __shfl_xor_sync(FULLM, s, off);
    if (lane == 0) g_partial[qi] = s;
}

__global__ __launch_bounds__(TPB, 1)
void knn_loss_kernel(const float* __restrict__ outputs,
                     const float* __restrict__ points,
                     float* __restrict__ out) {
    const int tid = threadIdx.x;
    const int lane = tid & 31;
    const int warp = tid >> 5;

    // cooperative smem fill: 8192 float2 = 4096 float4
    {
        float4* dst = (float4*)pts_s;
        const float4* src = (const float4*)points;
#pragma unroll
        for (int i = 0; i < NPTS / 2 / TPB; i++)
            dst[tid + i * TPB] = src[tid + i * TPB];
    }
    __syncthreads();

    const int qb = (blockIdx.x * WPB + warp) * QPW;
    const float2 q0 = pts_s[qb + 0];
    const float2 q1 = pts_s[qb + 1];
    const float2 q2 = pts_s[qb + 2];
    const float2 q3 = pts_s[qb + 3];

    TopK t0, t1, t2, t3;
    tk_init(t0); tk_init(t1); tk_init(t2); tk_init(t3);

#pragma unroll 4
    for (int tt = 0; tt < NPTS / 32; tt++) {
        const int jbase = tt * 32;
        float2 p = pts_s[jbase + lane];

        float dx, dy;
        dx = q0.x - p.x; dy = q0.y - p.y;
        float d20 = fmaf(dy, dy, dx * dx);
        dx = q1.x - p.x; dy = q1.y - p.y;
        float d21 = fmaf(dy, dy, dx * dx);
        dx = q2.x - p.x; dy = q2.y - p.y;
        float d22 = fmaf(dy, dy, dx * dx);
        dx = q3.x - p.x; dy = q3.y - p.y;
        float d23 = fmaf(dy, dy, dx * dx);

        unsigned m0 = __ballot_sync(FULLM, d20 < t0.th);
        unsigned m1 = __ballot_sync(FULLM, d21 < t1.th);
        unsigned m2 = __ballot_sync(FULLM, d22 < t2.th);
        unsigned m3 = __ballot_sync(FULLM, d23 < t3.th);
        if (m0) tk_hits(t0, m0, d20, jbase, lane);
        if (m1) tk_hits(t1, m1, d21, jbase, lane);
        if (m2) tk_hits(t2, m2, d22, jbase, lane);
        if (m3) tk_hits(t3, m3, d23, jbase, lane);
    }

    finish_query(t0, qb + 0, outputs, lane);
    finish_query(t1, qb + 1, outputs, lane);
    finish_query(t2, qb + 2, outputs, lane);
    finish_query(t3, qb + 3, outputs, lane);

    // ---- fused final reduction: last block to arrive does the sum ----
    __syncthreads();
    __shared__ bool is_last;
    if (tid == 0) {
        __threadfence();
        unsigned tk = atomicAdd(&g_ticket, 1);
        is_last = (tk == NBLK - 1);
    }
    __syncthreads();
    if (is_last) {
        __threadfence();
        float acc = 0.0f;
        for (int j = tid; j < NPTS; j += TPB) acc += g_partial[j];
        __shared__ float sm[TPB];
        sm[tid] = acc;
        __syncthreads();
        for (int st = TPB / 2; st > 0; st >>= 1) {
            if (tid < st) sm[tid] += sm[tid + st];
            __syncthreads();
        }
        if (tid == 0) {
            out[0] = sm[0] / (float)(NPTS * KNN);
            g_ticket = 0;  // reset for next graph replay
        }
    }
}

extern "C" void kernel_launch(void* const* d_in, const int* in_sizes, int n_in,
                              void* d_out, int out_size) {
    const float* outputs = (const float*)d_in[0];
    const float* points  = (const float*)d_in[1];
    float* out = (float*)d_out;

    cudaFuncSetAttribute(knn_loss_kernel,
                         cudaFuncAttributeMaxDynamicSharedMemorySize,
                         NPTS * sizeof(float2));
    knn_loss_kernel<<<NBLK, TPB, NPTS * sizeof(float2)>>>(outputs, points, out);
}

// round 5
// speedup vs baseline: 4.3916x; 2.2281x over previous
#include <cuda_runtime.h>
#include <cstdint>

// GeometricLoss: N=8192 2D points, k=5 NN (excl. self), mean of 16-ch L2 norms
// of output differences.
// R5: rank by f(p)=0.5|p|^2 - q.p (2 FFMA/candidate), smem tile of float4
// {x,y,h,pad}, distributed warp top-6, warp-min seeding of tile 0, TPB=1024
// (occ 50%), 2 queries/warp, fused last-block reduction.

#define NPTS 8192
#define NCH 16
#define KNN 5
#define TPB 1024
#define QPW 2                       // queries per warp
#define WPB (TPB / 32)              // 32 warps per block
#define QPB (WPB * QPW)             // 64 queries per block
#define NBLK (NPTS / QPB)           // 128 blocks
#define FULLM 0xFFFFFFFFu
#define SENT 0xFFFFFFFFFFFFFFFFULL

__device__ float g_partial[NPTS];
__device__ unsigned g_ticket = 0;

extern __shared__ float4 pts_s[];   // {x, y, 0.5*(x^2+y^2), pad}

// Monotone map: signed-float bits -> ascending u32.
__device__ __forceinline__ unsigned fmap(float f) {
    unsigned u = __float_as_uint(f);
    return (u & 0x80000000u) ? ~u : (u | 0x80000000u);
}
__device__ __forceinline__ float funmap(unsigned m) {
    unsigned u = (m & 0x80000000u) ? (m ^ 0x80000000u) : ~m;
    return __uint_as_float(u);
}

// Distributed top-6: lane r (r<6) holds rank-r key (fmap(f)<<32)|idx;
// th (replicated) is the 6th-best f. Keys unique & totally ordered ->
// exact, insertion-order-independent selection with low-index tie-break.
struct TopK {
    unsigned long long key;
    float th;
};

// Uniform insert (precondition: f < th). Sorted shift via shfl_up.
__device__ __forceinline__ void tk_insert(TopK& t, float f, int j, int lane) {
    unsigned long long nk =
        ((unsigned long long)fmap(f) << 32) | (unsigned)j;
    unsigned long long prev = __shfl_up_sync(FULLM, t.key, 1);
    bool shift = (lane > 0) && (nk < prev);
    bool take  = nk < t.key;
    t.key = shift ? prev : (take ? nk : t.key);
    t.th = funmap((unsigned)(__shfl_sync(FULLM, t.key, 5) >> 32));
}

// Slow path: walk ballot bits in increasing lane (=index) order, uniformly.
__device__ __forceinline__ void tk_hits(TopK& t, unsigned msk, float f,
                                        int jbase, int lane) {
    do {
        int src = __ffs(msk) - 1;
        msk &= msk - 1;
        float d = __shfl_sync(FULLM, f, src);
        if (d < t.th) tk_insert(t, d, jbase + src, lane);
    } while (msk);
}

// Seed from tile 0 (candidate j = lane): 6 warp-min extraction rounds.
__device__ __forceinline__ void tk_seed(TopK& t, float f, int lane) {
    unsigned long long v =
        ((unsigned long long)fmap(f) << 32) | (unsigned)lane;
    unsigned long long mykey = SENT;
#pragma unroll
    for (int r = 0; r < 6; r++) {
        unsigned long long m = v;
#pragma unroll
        for (int off = 16; off > 0; off >>= 1) {
            unsigned long long o = __shfl_xor_sync(FULLM, m, off);
            if (o < m) m = o;
        }
        if (lane == r) mykey = m;
        if (v == m) v = SENT;  // unique keys: exactly one owner retires
    }
    t.key = mykey;
    t.th = funmap((unsigned)(__shfl_sync(FULLM, t.key, 5) >> 32));
}

// Rank 0 is self; lanes 1..5 own the 5 neighbor keys.
__device__ __forceinline__ void finish_query(const TopK& t, int qi,
                                             const float* __restrict__ outputs,
                                             int lane) {
    float s = 0.0f;
    if (lane >= 1 && lane <= KNN) {
        int nb = (int)(t.key & 0xFFFFFFFFULL);
        const float4* oq = (const float4*)(outputs + (size_t)qi * NCH);
        const float4* on = (const float4*)(outputs + (size_t)nb * NCH);
        float acc = 0.0f;
#pragma unroll
        for (int c = 0; c < NCH / 4; c++) {
            float4 a = oq[c];
            float4 bb = on[c];
            float d;
            d = a.x - bb.x; acc = fmaf(d, d, acc);
            d = a.y - bb.y; acc = fmaf(d, d, acc);
            d = a.z - bb.z; acc = fmaf(d, d, acc);
            d = a.w - bb.w; acc = fmaf(d, d, acc);
        }
        s = sqrtf(acc);
    }
#pragma unroll
    for (int off = 16; off > 0; off >>= 1)
        s += __shfl_xor_sync(FULLM, s, off);
    if (lane == 0) g_partial[qi] = s;
}

__global__ __launch_bounds__(TPB, 1)
void knn_loss_kernel(const float* __restrict__ outputs,
                     const float* __restrict__ points,
                     float* __restrict__ out) {
    const int tid = threadIdx.x;
    const int lane = tid & 31;
    const int warp = tid >> 5;

    // cooperative smem fill: compute h = 0.5*(x^2+y^2) per point
    {
        const float2* src = (const float2*)points;
#pragma unroll
        for (int i = 0; i < NPTS / TPB; i++) {
            int j = tid + i * TPB;
            float2 p = src[j];
            float h = 0.5f * fmaf(p.y, p.y, p.x * p.x);
            pts_s[j] = make_float4(p.x, p.y, h, 0.0f);
        }
    }
    __syncthreads();

    const int qb = (blockIdx.x * WPB + warp) * QPW;
    const float4 Q0 = pts_s[qb + 0];
    const float4 Q1 = pts_s[qb + 1];
    const float nq0x = -Q0.x, nq0y = -Q0.y;
    const float nq1x = -Q1.x, nq1y = -Q1.y;

    TopK t0, t1;

    // ---- seed from tile 0 ----
    {
        float4 P = pts_s[lane];
        float f0 = fmaf(P.x, nq0x, fmaf(P.y, nq0y, P.z));
        float f1 = fmaf(P.x, nq1x, fmaf(P.y, nq1y, P.z));
        tk_seed(t0, f0, lane);
        tk_seed(t1, f1, lane);
    }

    // ---- main scan, tiles 1..255 ----
#pragma unroll 4
    for (int tt = 1; tt < NPTS / 32; tt++) {
        const int jbase = tt * 32;
        float4 P = pts_s[jbase + lane];
        float f0 = fmaf(P.x, nq0x, fmaf(P.y, nq0y, P.z));
        float f1 = fmaf(P.x, nq1x, fmaf(P.y, nq1y, P.z));
        unsigned m0 = __ballot_sync(FULLM, f0 < t0.th);
        unsigned m1 = __ballot_sync(FULLM, f1 < t1.th);
        if (m0) tk_hits(t0, m0, f0, jbase, lane);
        if (m1) tk_hits(t1, m1, f1, jbase, lane);
    }

    finish_query(t0, qb + 0, outputs, lane);
    finish_query(t1, qb + 1, outputs, lane);

    // ---- fused final reduction: last block to arrive does the sum ----
    __syncthreads();
    __shared__ bool is_last;
    if (tid == 0) {
        __threadfence();
        unsigned tk = atomicAdd(&g_ticket, 1);
        is_last = (tk == NBLK - 1);
    }
    __syncthreads();
    if (is_last) {
        __threadfence();
        float acc = 0.0f;
        for (int j = tid; j < NPTS; j += TPB) acc += g_partial[j];
        __shared__ float sm[TPB];
        sm[tid] = acc;
        __syncthreads();
        for (int st = TPB / 2; st > 0; st >>= 1) {
            if (tid < st) sm[tid] += sm[tid + st];
            __syncthreads();
        }
        if (tid == 0) {
            out[0] = sm[0] / (float)(NPTS * KNN);
            g_ticket = 0;  // reset for next graph replay
        }
    }
}

extern "C" void kernel_launch(void* const* d_in, const int* in_sizes, int n_in,
                              void* d_out, int out_size) {
    const float* outputs = (const float*)d_in[0];
    const float* points  = (const float*)d_in[1];
    float* out = (float*)d_out;

    cudaFuncSetAttribute(knn_loss_kernel,
                         cudaFuncAttributeMaxDynamicSharedMemorySize,
                         NPTS * sizeof(float4));
    knn_loss_kernel<<<NBLK, TPB, NPTS * sizeof(float4)>>>(outputs, points, out);
}